// round 13
// baseline (speedup 1.0000x reference)
#include <cuda_runtime.h>
#include <cstdint>

// Problem dims (fixed by the reference setup)
#define NB 4      // batch
#define NQ 16     // queries used (of 20)
#define NQP 20    // queries stored in btn_dec
#define NT 8      // t
#define NHW 256   // h*w
#define HWT 8     // hw positions per tile (4 tiles per block)
#define QT 8      // q positions per block
#define NG 8      // heads

__device__ __forceinline__ void ffma2(unsigned long long& d,
                                      unsigned long long a,
                                      unsigned long long b) {
    asm("fma.rn.f32x2 %0, %1, %2, %0;" : "+l"(d) : "l"(a), "l"(b));
}
__device__ __forceinline__ unsigned long long pack2(float lo, float hi) {
    unsigned long long r;
    asm("mov.b64 %0, {%1, %2};" : "=l"(r) : "f"(lo), "f"(hi));
    return r;
}
__device__ __forceinline__ void unpack2(unsigned long long v, float& lo, float& hi) {
    asm("mov.b64 {%0, %1}, %2;" : "=f"(lo), "=f"(hi) : "l"(v));
}
// 16B async copy gmem -> smem (bypasses registers)
__device__ __forceinline__ void cp16(uint32_t saddr, const void* gptr) {
    asm volatile("cp.async.cg.shared.global [%0], [%1], 16;"
                 :: "r"(saddr), "l"(gptr));
}
__device__ __forceinline__ void cp_commit() {
    asm volatile("cp.async.commit_group;");
}
__device__ __forceinline__ void cp_wait_all() {
    asm volatile("cp.async.wait_group 0;");
}

// Swizzled float4-index within a 512-float row (head g, chunk c4 0..15):
// (c4+g)&15 skew -> conflict-free g-parallel reads, 1-cyc dec broadcasts.
__device__ __forceinline__ int sw_idx(int g, int c4) {
    return g * 16 + ((c4 + g) & 15);
}

// ---------------------------------------------------------------------------
// Fused kernel, 4-tile rolling pipeline, SINGLE WAVE.
// Grid: 512 blocks = (b:4) x (t:8) x (qh:2) x (hw-octant:8), 128 threads,
// 52KB smem -> 4 blk/SM capacity (592) >= 512 blocks: all resident at once.
//
// Each block: 4 tiles of 8 hw sharing one dec tile. Per-iteration timeline:
//   B(t_i) rows 0..31  ⊗ cp.async enc(t_{i+1})      [stores flow]
//   B(t_i) rows 32..63 ⊗ A(t_{i+1}) -> sc[nxt]      [stores flow]
// Store-idle work (initial stage + A(t0)) is paid ONCE per 256 rows.
// ---------------------------------------------------------------------------
__global__ void __launch_bounds__(128, 4) heatmap_fused(
    const float* __restrict__ dec,   // (4, 20, 8, 512)
    const float* __restrict__ enc,   // (4, 8, 256, 512)
    const float* __restrict__ Wm,    // (8, 512)
    const float* __restrict__ bias,  // (512,)
    float* __restrict__ out)         // (4, 16, 8, 256, 512)
{
    extern __shared__ char smem_raw[];
    ulonglong2* dec_s = reinterpret_cast<ulonglong2*>(smem_raw);             // 16 KB
    ulonglong2* enc_sbuf[2] = {
        reinterpret_cast<ulonglong2*>(smem_raw + 16384),                     // 16 KB
        reinterpret_cast<ulonglong2*>(smem_raw + 32768) };                   // 16 KB
    float* sc_buf[2] = {
        reinterpret_cast<float*>(smem_raw + 49152),                          //  2 KB
        reinterpret_cast<float*>(smem_raw + 51200) };                        //  2 KB

    const int tid = threadIdx.x;
    const int bid = blockIdx.x;
    const int oct = bid & 7;             // hw octant: hw base = oct*32
    const int qh  = (bid >> 3) & 1;      // q0 = qh*8
    const int t   = (bid >> 4) & 7;
    const int b   = bid >> 7;
    const int hwb = oct * 32;

    const uint32_t dec_sb = (uint32_t)__cvta_generic_to_shared(dec_s);
    const uint32_t enc_sb[2] = {
        (uint32_t)__cvta_generic_to_shared(enc_sbuf[0]),
        (uint32_t)__cvta_generic_to_shared(enc_sbuf[1]) };

    const float* encg_base = enc + ((size_t)((b * NT + t) * NHW + hwb)) * 512;

    // ---- prologue: cp.async enc(t0) + dec, swizzled ----
    {
#pragma unroll
        for (int k = 0; k < 8; k++) {
            int i = tid + k * 128;           // 0..1023
            int hwl = i >> 7;
            int j   = i & 127;
            cp16(enc_sb[0] + (hwl * 128 + sw_idx(j >> 4, j & 15)) * 16,
                 encg_base + (size_t)i * 4);
        }
#pragma unroll
        for (int k = 0; k < 8; k++) {
            int i = tid + k * 128;           // 0..1023
            int q = i >> 7;                  // local q 0..7
            int j = i & 127;
            cp16(dec_sb + (q * 128 + sw_idx(j >> 4, j & 15)) * 16,
                 dec + ((size_t)((b * NQP + qh * QT + q) * NT + t)) * 512 + j * 4);
        }
        cp_commit();
    }

    // W/bias into registers while cp.async is in flight
    const int f4 = tid;
    const unsigned long long* W2 = reinterpret_cast<const unsigned long long*>(Wm);
    unsigned long long wreg[NG][2];
#pragma unroll
    for (int g = 0; g < NG; g++) {
        wreg[g][0] = W2[g * 256 + f4 * 2];
        wreg[g][1] = W2[g * 256 + f4 * 2 + 1];
    }
    const unsigned long long* B2 = reinterpret_cast<const unsigned long long*>(bias);
    const unsigned long long bb0 = B2[f4 * 2];
    const unsigned long long bb1 = B2[f4 * 2 + 1];

    cp_wait_all();
    __syncthreads();

    // Phase-A thread mapping: (qsub:2, hw:8, g:8), 4 q accumulators
    const int ga   = tid & 7;
    const int hwa  = (tid >> 3) & 7;
    const int qsub = tid >> 6;
    const ulonglong2* drow = dec_s + qsub * 4 * 128;

    // ---- A(t0) -> sc[0] ----
    {
        unsigned long long acc[4];
#pragma unroll
        for (int q = 0; q < 4; q++) acc[q] = 0ull;
        const ulonglong2* erow = enc_sbuf[0] + hwa * 128;
#pragma unroll 4
        for (int c4 = 0; c4 < 16; c4++) {
            const int cc = sw_idx(ga, c4);
            ulonglong2 e = erow[cc];
#pragma unroll
            for (int qq = 0; qq < 4; qq++) {
                ulonglong2 d = drow[qq * 128 + cc];
                ffma2(acc[qq], e.x, d.x);
                ffma2(acc[qq], e.y, d.y);
            }
        }
#pragma unroll
        for (int qq = 0; qq < 4; qq++) {
            float lo, hi;
            unpack2(acc[qq], lo, hi);
            sc_buf[0][((qsub * 4 + qq) * HWT + hwa) * NG + ga] = lo + hi;
        }
    }
    __syncthreads();

    // out float4 base for tile0 (q-local stride 262144, hwl stride 128)
    float4* outB = reinterpret_cast<float4*>(out)
        + ((size_t)((b * NQ + qh * QT) * NT + t) * NHW + hwb) * 128 + f4;

#define B_ROW(scf, r, obase)                                                       \
    {                                                                              \
        float4 sA = (scf)[(r) * 2 + 0];                                            \
        float4 sB = (scf)[(r) * 2 + 1];                                            \
        unsigned long long a0 = bb0, a1 = bb1;                                     \
        unsigned long long sp;                                                     \
        sp = pack2(sA.x, sA.x); ffma2(a0, sp, wreg[0][0]); ffma2(a1, sp, wreg[0][1]); \
        sp = pack2(sA.y, sA.y); ffma2(a0, sp, wreg[1][0]); ffma2(a1, sp, wreg[1][1]); \
        sp = pack2(sA.z, sA.z); ffma2(a0, sp, wreg[2][0]); ffma2(a1, sp, wreg[2][1]); \
        sp = pack2(sA.w, sA.w); ffma2(a0, sp, wreg[3][0]); ffma2(a1, sp, wreg[3][1]); \
        sp = pack2(sB.x, sB.x); ffma2(a0, sp, wreg[4][0]); ffma2(a1, sp, wreg[4][1]); \
        sp = pack2(sB.y, sB.y); ffma2(a0, sp, wreg[5][0]); ffma2(a1, sp, wreg[5][1]); \
        sp = pack2(sB.z, sB.z); ffma2(a0, sp, wreg[6][0]); ffma2(a1, sp, wreg[6][1]); \
        sp = pack2(sB.w, sB.w); ffma2(a0, sp, wreg[7][0]); ffma2(a1, sp, wreg[7][1]); \
        float4 res;                                                                \
        asm("mov.b64 {%0, %1}, %2;" : "=f"(res.x), "=f"(res.y) : "l"(a0));         \
        asm("mov.b64 {%0, %1}, %2;" : "=f"(res.z), "=f"(res.w) : "l"(a1));         \
        res.x = fmaxf(res.x, 0.f);                                                 \
        res.y = fmaxf(res.y, 0.f);                                                 \
        res.z = fmaxf(res.z, 0.f);                                                 \
        res.w = fmaxf(res.w, 0.f);                                                 \
        const int q_   = (r) >> 3;                                                 \
        const int hwl_ = (r) & 7;                                                  \
        __stcs(&(obase)[(size_t)q_ * 262144 + hwl_ * 128], res);                   \
    }

    // ---- rolling pipeline over 4 tiles ----
#pragma unroll
    for (int i = 0; i < 4; i++) {
        const int cur = i & 1;
        const int nxt = cur ^ 1;
        const bool more = (i < 3);
        const float4* scf = reinterpret_cast<const float4*>(sc_buf[cur]);
        float4* outT = outB + (size_t)(i * HWT) * 128;

        // Section 1: B rows 0..31  ⊗  cp.async enc(t_{i+1}) into buffer nxt
        {
            const float* encg1 = encg_base + (size_t)((i + 1) * HWT) * 512;
#pragma unroll 4
            for (int rr = 0; rr < 32; rr++) {
                if (more && (rr & 3) == 0) {
                    int k = rr >> 2;                 // 0..7
                    int ii = tid + k * 128;          // 0..1023
                    int hwl = ii >> 7;
                    int j   = ii & 127;
                    cp16(enc_sb[nxt] + (hwl * 128 + sw_idx(j >> 4, j & 15)) * 16,
                         encg1 + (size_t)ii * 4);
                }
                B_ROW(scf, rr, outT);
            }
            if (more) { cp_commit(); cp_wait_all(); }
        }
        __syncthreads();

        // Section 2: B rows 32..63  ⊗  A(t_{i+1}) -> sc[nxt]
        {
            unsigned long long acc2[4];
#pragma unroll
            for (int q = 0; q < 4; q++) acc2[q] = 0ull;
            const ulonglong2* erow = enc_sbuf[nxt] + hwa * 128;

#pragma unroll 2
            for (int s = 0; s < 16; s++) {
                if (more) {
                    const int cc = sw_idx(ga, s);
                    ulonglong2 e = erow[cc];
#pragma unroll
                    for (int qq = 0; qq < 4; qq++) {
                        ulonglong2 d = drow[qq * 128 + cc];
                        ffma2(acc2[qq], e.x, d.x);
                        ffma2(acc2[qq], e.y, d.y);
                    }
                }
                B_ROW(scf, 32 + s * 2 + 0, outT);
                B_ROW(scf, 32 + s * 2 + 1, outT);
            }
            if (more) {
#pragma unroll
                for (int qq = 0; qq < 4; qq++) {
                    float lo, hi;
                    unpack2(acc2[qq], lo, hi);
                    sc_buf[nxt][((qsub * 4 + qq) * HWT + hwa) * NG + ga] = lo + hi;
                }
            }
        }
        __syncthreads();
    }
#undef B_ROW
}

extern "C" void kernel_launch(void* const* d_in, const int* in_sizes, int n_in,
                              void* d_out, int out_size)
{
    const float* dec  = (const float*)d_in[0];  // (4,20,8,512)
    const float* enc  = (const float*)d_in[1];  // (4,8,16,16,512)
    const float* Wm   = (const float*)d_in[2];  // (8,512)
    const float* bias = (const float*)d_in[3];  // (512,)
    float* out = (float*)d_out;                 // (4,16,8,16,16,512)

    const int smem = 52 * 1024;
    cudaFuncSetAttribute(heatmap_fused,
                         cudaFuncAttributeMaxDynamicSharedMemorySize, smem);

    // 512 blocks = (b:4)x(t:8)x(qh:2)x(hw-octant:8), 4 tiles each
    heatmap_fused<<<NB * NT * 2 * (NHW / 32), 128, smem>>>(dec, enc, Wm, bias, out);
}

// round 14
// speedup vs baseline: 1.0397x; 1.0397x over previous
#include <cuda_runtime.h>

// Problem dims (fixed by the reference setup)
#define NB 4      // batch
#define NQ 16     // queries used (of 20)
#define NQP 20    // queries stored in btn_dec
#define NT 8      // t
#define NHW 256   // h*w
#define HWT 16    // hw positions per block
#define QT 8      // q positions per block (2 halves of 4)
#define NG 8      // heads
#define NF 512    // btn_features

__device__ __forceinline__ void ffma2(unsigned long long& d,
                                      unsigned long long a,
                                      unsigned long long b) {
    asm("fma.rn.f32x2 %0, %1, %2, %0;" : "+l"(d) : "l"(a), "l"(b));
}
__device__ __forceinline__ unsigned long long pack2(float lo, float hi) {
    unsigned long long r;
    asm("mov.b64 %0, {%1, %2};" : "=l"(r) : "f"(lo), "f"(hi));
    return r;
}
__device__ __forceinline__ void unpack2(unsigned long long v, float& lo, float& hi) {
    asm("mov.b64 {%0, %1}, %2;" : "=f"(lo), "=f"(hi) : "l"(v));
}

// Swizzled float4-index within a 512-float row (head g, chunk c4 0..15):
// (c4+g)&15 skew -> conflict-free g-parallel reads, 1-cyc dec broadcasts.
__device__ __forceinline__ int sw_idx(int g, int c4) {
    return g * 16 + ((c4 + g) & 15);
}

// ---------------------------------------------------------------------------
// Fused kernel, software-pipelined (R11 structure, proven best at 47.6us).
// ONE change: plain write-back STG.128 instead of __stcs (evict-first).
// Grid: 1024 blocks = (b:4) x (t:8) x (hwtile:16) x (qh:2), 128 threads,
// 52KB smem -> 4 blk/SM.
// ---------------------------------------------------------------------------
__global__ void __launch_bounds__(128, 4) heatmap_fused(
    const float* __restrict__ dec,   // (4, 20, 8, 512)
    const float* __restrict__ enc,   // (4, 8, 256, 512)
    const float* __restrict__ Wm,    // (8, 512)
    const float* __restrict__ bias,  // (512,)
    float* __restrict__ out)         // (4, 16, 8, 256, 512)
{
    extern __shared__ char smem_raw[];
    ulonglong2* enc_s = reinterpret_cast<ulonglong2*>(smem_raw);            // 32 KB
    ulonglong2* dec_s = reinterpret_cast<ulonglong2*>(smem_raw + 32768);    // 16 KB
    float*      sc0   = reinterpret_cast<float*>(smem_raw + 49152);         //  2 KB
    float*      sc1   = reinterpret_cast<float*>(smem_raw + 51200);         //  2 KB

    const int tid = threadIdx.x;
    const int bid = blockIdx.x;
    const int qh  = bid & 1;             // q half-of-16: q0 = qh*8
    const int hwt = (bid >> 1) & 15;     // hw tile (16 positions)
    const int t   = (bid >> 5) & 7;
    const int b   = bid >> 8;

    // ---- stage enc tile: 16 hw rows x 128 float4, swizzled ----
    {
        const ulonglong2* encg = reinterpret_cast<const ulonglong2*>(enc)
            + ((size_t)((b * NT + t) * NHW + hwt * HWT)) * 128;
#pragma unroll
        for (int k = 0; k < 16; k++) {
            int i = tid + k * 128;           // 0..2047
            int hwl = i >> 7;
            int j   = i & 127;
            enc_s[hwl * 128 + sw_idx(j >> 4, j & 15)] = encg[i];
        }
    }
    // ---- stage dec tile: 8 q rows x 128 float4, swizzled ----
    {
#pragma unroll
        for (int k = 0; k < 8; k++) {
            int i = tid + k * 128;           // 0..1023
            int q = i >> 7;                  // local q 0..7
            int j = i & 127;
            const ulonglong2* decg = reinterpret_cast<const ulonglong2*>(dec)
                + ((size_t)((b * NQP + qh * QT + q) * NT + t)) * 128;
            dec_s[q * 128 + sw_idx(j >> 4, j & 15)] = decg[j];
        }
    }
    __syncthreads();

    // Phase-A thread mapping (persistent across both halves)
    const int ga  = tid & 7;
    const int hwa = tid >> 3;               // 0..15
    const ulonglong2* erow = enc_s + hwa * 128;

    // ---- A(q0..3) -> sc0 ----
    {
        unsigned long long acc[4];
#pragma unroll
        for (int q = 0; q < 4; q++) acc[q] = 0ull;
#pragma unroll 4
        for (int c4 = 0; c4 < 16; c4++) {
            const int cc = sw_idx(ga, c4);
            ulonglong2 e = erow[cc];
#pragma unroll
            for (int q = 0; q < 4; q++) {
                ulonglong2 d = dec_s[q * 128 + cc];
                ffma2(acc[q], e.x, d.x);
                ffma2(acc[q], e.y, d.y);
            }
        }
#pragma unroll
        for (int q = 0; q < 4; q++) {
            float lo, hi;
            unpack2(acc[q], lo, hi);
            sc0[(q * HWT + hwa) * NG + ga] = lo + hi;
        }
    }

    // W/bias into registers (overlaps phase-A tail)
    const int f4 = tid;
    const unsigned long long* W2 = reinterpret_cast<const unsigned long long*>(Wm);
    unsigned long long wreg[NG][2];
#pragma unroll
    for (int g = 0; g < NG; g++) {
        wreg[g][0] = W2[g * 256 + f4 * 2];
        wreg[g][1] = W2[g * 256 + f4 * 2 + 1];
    }
    const unsigned long long* B2 = reinterpret_cast<const unsigned long long*>(bias);
    const unsigned long long bb0 = B2[f4 * 2];
    const unsigned long long bb1 = B2[f4 * 2 + 1];

    __syncthreads();

    // out float4 base: (((b*16 + qh*8)*8+t)*256 + hwt*16)*128 + f4
    float4* out4 = reinterpret_cast<float4*>(out)
        + ((size_t)((b * NQ + qh * QT) * NT + t) * NHW + hwt * HWT) * 128 + f4;
    // local q stride (float4): 8*256*128 = 262144 ; hwl stride: 128

#define B_ROW(scf, r, qofs)                                                        \
    {                                                                              \
        float4 sA = (scf)[(r) * 2 + 0];                                            \
        float4 sB = (scf)[(r) * 2 + 1];                                            \
        unsigned long long a0 = bb0, a1 = bb1;                                     \
        unsigned long long sp;                                                     \
        sp = pack2(sA.x, sA.x); ffma2(a0, sp, wreg[0][0]); ffma2(a1, sp, wreg[0][1]); \
        sp = pack2(sA.y, sA.y); ffma2(a0, sp, wreg[1][0]); ffma2(a1, sp, wreg[1][1]); \
        sp = pack2(sA.z, sA.z); ffma2(a0, sp, wreg[2][0]); ffma2(a1, sp, wreg[2][1]); \
        sp = pack2(sA.w, sA.w); ffma2(a0, sp, wreg[3][0]); ffma2(a1, sp, wreg[3][1]); \
        sp = pack2(sB.x, sB.x); ffma2(a0, sp, wreg[4][0]); ffma2(a1, sp, wreg[4][1]); \
        sp = pack2(sB.y, sB.y); ffma2(a0, sp, wreg[5][0]); ffma2(a1, sp, wreg[5][1]); \
        sp = pack2(sB.z, sB.z); ffma2(a0, sp, wreg[6][0]); ffma2(a1, sp, wreg[6][1]); \
        sp = pack2(sB.w, sB.w); ffma2(a0, sp, wreg[7][0]); ffma2(a1, sp, wreg[7][1]); \
        float4 res;                                                                \
        asm("mov.b64 {%0, %1}, %2;" : "=f"(res.x), "=f"(res.y) : "l"(a0));         \
        asm("mov.b64 {%0, %1}, %2;" : "=f"(res.z), "=f"(res.w) : "l"(a1));         \
        res.x = fmaxf(res.x, 0.f);                                                 \
        res.y = fmaxf(res.y, 0.f);                                                 \
        res.z = fmaxf(res.z, 0.f);                                                 \
        res.w = fmaxf(res.w, 0.f);                                                 \
        const int q_   = ((r) >> 4) + (qofs);                                      \
        const int hwl_ = (r) & 15;                                                 \
        out4[(size_t)q_ * 262144 + hwl_ * 128] = res;                              \
    }

    // ---- INTERLEAVED: A(q4..7) c4-steps woven between B(q0..3) rows ----
    {
        unsigned long long acc2[4];
#pragma unroll
        for (int q = 0; q < 4; q++) acc2[q] = 0ull;

        const float4* scf0 = reinterpret_cast<const float4*>(sc0);

#pragma unroll 2
        for (int s = 0; s < 16; s++) {
            // one c4-step of A(q4..7) — registers only
            const int cc = sw_idx(ga, s);
            ulonglong2 e = erow[cc];
#pragma unroll
            for (int q = 0; q < 4; q++) {
                ulonglong2 d = dec_s[(4 + q) * 128 + cc];
                ffma2(acc2[q], e.x, d.x);
                ffma2(acc2[q], e.y, d.y);
            }
            // four B rows of q0..3 — stores
#pragma unroll
            for (int rr = 0; rr < 4; rr++) {
                B_ROW(scf0, s * 4 + rr, 0);
            }
        }

        // flush A(q4..7) accumulators to the second score buffer
#pragma unroll
        for (int q = 0; q < 4; q++) {
            float lo, hi;
            unpack2(acc2[q], lo, hi);
            sc1[(q * HWT + hwa) * NG + ga] = lo + hi;
        }
    }
    __syncthreads();

    // ---- B(q4..7) from sc1 ----
    {
        const float4* scf1 = reinterpret_cast<const float4*>(sc1);
#pragma unroll 4
        for (int r = 0; r < 64; r++) {
            B_ROW(scf1, r, 4);
        }
    }
#undef B_ROW
}

extern "C" void kernel_launch(void* const* d_in, const int* in_sizes, int n_in,
                              void* d_out, int out_size)
{
    const float* dec  = (const float*)d_in[0];  // (4,20,8,512)
    const float* enc  = (const float*)d_in[1];  // (4,8,16,16,512)
    const float* Wm   = (const float*)d_in[2];  // (8,512)
    const float* bias = (const float*)d_in[3];  // (512,)
    float* out = (float*)d_out;                 // (4,16,8,16,16,512)

    const int smem = 52 * 1024;
    cudaFuncSetAttribute(heatmap_fused,
                         cudaFuncAttributeMaxDynamicSharedMemorySize, smem);

    // 1024 blocks = (b:4)x(t:8)x(hwtile:16)x(qh:2)
    heatmap_fused<<<NB * NT * (NHW / HWT) * 2, 128, smem>>>(dec, enc, Wm, bias, out);
}

// round 15
// speedup vs baseline: 1.1190x; 1.0763x over previous
#include <cuda_runtime.h>

// Problem dims (fixed by the reference setup)
#define NB 4      // batch
#define NQ 16     // queries used (of 20)
#define NQP 20    // queries stored in btn_dec
#define NT 8      // t
#define NHW 256   // h*w
#define HWT 16    // hw positions per block
#define QT 8      // q positions per block
#define NG 8      // heads

__device__ __forceinline__ void ffma2(unsigned long long& d,
                                      unsigned long long a,
                                      unsigned long long b) {
    asm("fma.rn.f32x2 %0, %1, %2, %0;" : "+l"(d) : "l"(a), "l"(b));
}
__device__ __forceinline__ unsigned long long pack2(float lo, float hi) {
    unsigned long long r;
    asm("mov.b64 %0, {%1, %2};" : "=l"(r) : "f"(lo), "f"(hi));
    return r;
}
__device__ __forceinline__ void unpack2(unsigned long long v, float& lo, float& hi) {
    asm("mov.b64 {%0, %1}, %2;" : "=f"(lo), "=f"(hi) : "l"(v));
}

// Swizzled float4-index within a 512-float row (head g, chunk c4 0..15):
// (c4+g)&15 skew -> conflict-free g-parallel reads, 1-cyc dec broadcasts.
__device__ __forceinline__ int sw_idx(int g, int c4) {
    return g * 16 + ((c4 + g) & 15);
}

// ---------------------------------------------------------------------------
// Fused kernel, PER-Q software pipeline (refines proven R11, 47.6us).
// Grid: 1024 blocks = (b:4) x (t:8) x (hwtile:16) x (qh:2), 128 threads,
// ~50KB smem -> 4 blk/SM. Streaming __stcs stores (R14 proved .cs wins).
//
// Timeline per block:
//   stage enc(32KB)+dec(16KB)              [store-idle]
//   A(q0) -> sc[0]                         [store-idle, 1/8 of A only]
//   for q = 0..7:
//     weave A(q+1)->sc[nxt] 1:1 with B(q)'s 16 store rows   [stores flow]
// Exposed store-idle work drops from (staging + A/2) to (staging + A/8).
// ---------------------------------------------------------------------------
__global__ void __launch_bounds__(128, 4) heatmap_fused(
    const float* __restrict__ dec,   // (4, 20, 8, 512)
    const float* __restrict__ enc,   // (4, 8, 256, 512)
    const float* __restrict__ Wm,    // (8, 512)
    const float* __restrict__ bias,  // (512,)
    float* __restrict__ out)         // (4, 16, 8, 256, 512)
{
    extern __shared__ char smem_raw[];
    ulonglong2* enc_s = reinterpret_cast<ulonglong2*>(smem_raw);            // 32 KB
    ulonglong2* dec_s = reinterpret_cast<ulonglong2*>(smem_raw + 32768);    // 16 KB
    float* sc_buf[2] = {
        reinterpret_cast<float*>(smem_raw + 49152),                         // 512 B
        reinterpret_cast<float*>(smem_raw + 49664) };                       // 512 B

    const int tid = threadIdx.x;
    const int bid = blockIdx.x;
    const int qh  = bid & 1;             // q half-of-16: q0 = qh*8
    const int hwt = (bid >> 1) & 15;     // hw tile (16 positions)
    const int t   = (bid >> 5) & 7;
    const int b   = bid >> 8;

    // ---- stage enc tile: 16 hw rows x 128 float4, swizzled ----
    {
        const ulonglong2* encg = reinterpret_cast<const ulonglong2*>(enc)
            + ((size_t)((b * NT + t) * NHW + hwt * HWT)) * 128;
#pragma unroll
        for (int k = 0; k < 16; k++) {
            int i = tid + k * 128;           // 0..2047
            int hwl = i >> 7;
            int j   = i & 127;
            enc_s[hwl * 128 + sw_idx(j >> 4, j & 15)] = encg[i];
        }
    }
    // ---- stage dec tile: 8 q rows x 128 float4, swizzled ----
    {
#pragma unroll
        for (int k = 0; k < 8; k++) {
            int i = tid + k * 128;           // 0..1023
            int q = i >> 7;                  // local q 0..7
            int j = i & 127;
            const ulonglong2* decg = reinterpret_cast<const ulonglong2*>(dec)
                + ((size_t)((b * NQP + qh * QT + q) * NT + t)) * 128;
            dec_s[q * 128 + sw_idx(j >> 4, j & 15)] = decg[j];
        }
    }

    // W/bias into registers (overlaps staging latency)
    const int f4 = tid;
    const unsigned long long* W2 = reinterpret_cast<const unsigned long long*>(Wm);
    unsigned long long wreg[NG][2];
#pragma unroll
    for (int g = 0; g < NG; g++) {
        wreg[g][0] = W2[g * 256 + f4 * 2];
        wreg[g][1] = W2[g * 256 + f4 * 2 + 1];
    }
    const unsigned long long* B2 = reinterpret_cast<const unsigned long long*>(bias);
    const unsigned long long bb0 = B2[f4 * 2];
    const unsigned long long bb1 = B2[f4 * 2 + 1];

    __syncthreads();

    // Phase-A thread mapping: thread = (hwl:16, g:8), ONE q per pass
    const int ga  = tid & 7;
    const int hwa = tid >> 3;               // 0..15
    const ulonglong2* erow = enc_s + hwa * 128;

    // ---- A(q0) -> sc[0]  (the only exposed A work) ----
    {
        unsigned long long acc = 0ull;
#pragma unroll
        for (int c4 = 0; c4 < 16; c4++) {
            const int cc = sw_idx(ga, c4);
            ulonglong2 e = erow[cc];
            ulonglong2 d = dec_s[cc];        // q = 0
            ffma2(acc, e.x, d.x);
            ffma2(acc, e.y, d.y);
        }
        float lo, hi;
        unpack2(acc, lo, hi);
        sc_buf[0][hwa * NG + ga] = lo + hi;
    }
    __syncthreads();

    // out float4 base: (((b*16 + qh*8)*8+t)*256 + hwt*16)*128 + f4
    float4* out4 = reinterpret_cast<float4*>(out)
        + ((size_t)((b * NQ + qh * QT) * NT + t) * NHW + hwt * HWT) * 128 + f4;
    // local q stride (float4): 8*256*128 = 262144 ; hwl stride: 128

#define B_ROW(scf, hwl_, q_)                                                       \
    {                                                                              \
        float4 sA = (scf)[(hwl_) * 2 + 0];                                         \
        float4 sB = (scf)[(hwl_) * 2 + 1];                                         \
        unsigned long long a0 = bb0, a1 = bb1;                                     \
        unsigned long long sp;                                                     \
        sp = pack2(sA.x, sA.x); ffma2(a0, sp, wreg[0][0]); ffma2(a1, sp, wreg[0][1]); \
        sp = pack2(sA.y, sA.y); ffma2(a0, sp, wreg[1][0]); ffma2(a1, sp, wreg[1][1]); \
        sp = pack2(sA.z, sA.z); ffma2(a0, sp, wreg[2][0]); ffma2(a1, sp, wreg[2][1]); \
        sp = pack2(sA.w, sA.w); ffma2(a0, sp, wreg[3][0]); ffma2(a1, sp, wreg[3][1]); \
        sp = pack2(sB.x, sB.x); ffma2(a0, sp, wreg[4][0]); ffma2(a1, sp, wreg[4][1]); \
        sp = pack2(sB.y, sB.y); ffma2(a0, sp, wreg[5][0]); ffma2(a1, sp, wreg[5][1]); \
        sp = pack2(sB.z, sB.z); ffma2(a0, sp, wreg[6][0]); ffma2(a1, sp, wreg[6][1]); \
        sp = pack2(sB.w, sB.w); ffma2(a0, sp, wreg[7][0]); ffma2(a1, sp, wreg[7][1]); \
        float4 res;                                                                \
        asm("mov.b64 {%0, %1}, %2;" : "=f"(res.x), "=f"(res.y) : "l"(a0));         \
        asm("mov.b64 {%0, %1}, %2;" : "=f"(res.z), "=f"(res.w) : "l"(a1));         \
        res.x = fmaxf(res.x, 0.f);                                                 \
        res.y = fmaxf(res.y, 0.f);                                                 \
        res.z = fmaxf(res.z, 0.f);                                                 \
        res.w = fmaxf(res.w, 0.f);                                                 \
        __stcs(&out4[(size_t)(q_) * 262144 + (hwl_) * 128], res);                  \
    }

    // ---- per-q pipeline: A(q+1) woven 1:1 into B(q)'s 16 rows ----
#pragma unroll
    for (int q = 0; q < QT; q++) {
        const int cur = q & 1;
        const int nxt = cur ^ 1;
        const bool more = (q < QT - 1);
        const float4* scf = reinterpret_cast<const float4*>(sc_buf[cur]);
        const ulonglong2* drow = dec_s + (q + 1) * 128;   // next q's dec row

        unsigned long long acc = 0ull;
#pragma unroll
        for (int s = 0; s < 16; s++) {
            if (more) {
                const int cc = sw_idx(ga, s);
                ulonglong2 e = erow[cc];
                ulonglong2 d = drow[cc];
                ffma2(acc, e.x, d.x);
                ffma2(acc, e.y, d.y);
            }
            B_ROW(scf, s, q);
        }
        if (more) {
            float lo, hi;
            unpack2(acc, lo, hi);
            sc_buf[nxt][hwa * NG + ga] = lo + hi;
        }
        __syncthreads();
    }
#undef B_ROW
}

extern "C" void kernel_launch(void* const* d_in, const int* in_sizes, int n_in,
                              void* d_out, int out_size)
{
    const float* dec  = (const float*)d_in[0];  // (4,20,8,512)
    const float* enc  = (const float*)d_in[1];  // (4,8,16,16,512)
    const float* Wm   = (const float*)d_in[2];  // (8,512)
    const float* bias = (const float*)d_in[3];  // (512,)
    float* out = (float*)d_out;                 // (4,16,8,16,16,512)

    const int smem = 52 * 1024;
    cudaFuncSetAttribute(heatmap_fused,
                         cudaFuncAttributeMaxDynamicSharedMemorySize, smem);

    // 1024 blocks = (b:4)x(t:8)x(hwtile:16)x(qh:2)
    heatmap_fused<<<NB * NT * (NHW / HWT) * 2, 128, smem>>>(dec, enc, Wm, bias, out);
}

// round 16
// speedup vs baseline: 1.2081x; 1.0796x over previous
#include <cuda_runtime.h>
#include <cstdint>

// Problem dims (fixed by the reference setup)
#define NB 4      // batch
#define NQ 16     // queries used (of 20)
#define NQP 20    // queries stored in btn_dec
#define NT 8      // t
#define NHW 256   // h*w
#define HWT 16    // hw positions per block
#define QT 8      // q positions per block (2 halves of 4)
#define NG 8      // heads

__device__ __forceinline__ void ffma2(unsigned long long& d,
                                      unsigned long long a,
                                      unsigned long long b) {
    asm("fma.rn.f32x2 %0, %1, %2, %0;" : "+l"(d) : "l"(a), "l"(b));
}
__device__ __forceinline__ unsigned long long pack2(float lo, float hi) {
    unsigned long long r;
    asm("mov.b64 %0, {%1, %2};" : "=l"(r) : "f"(lo), "f"(hi));
    return r;
}
__device__ __forceinline__ void unpack2(unsigned long long v, float& lo, float& hi) {
    asm("mov.b64 {%0, %1}, %2;" : "=f"(lo), "=f"(hi) : "l"(v));
}
// 16B async copy gmem -> smem (bypasses registers)
__device__ __forceinline__ void cp16(uint32_t saddr, const void* gptr) {
    asm volatile("cp.async.cg.shared.global [%0], [%1], 16;"
                 :: "r"(saddr), "l"(gptr));
}
__device__ __forceinline__ void cp_commit() {
    asm volatile("cp.async.commit_group;");
}
__device__ __forceinline__ void cp_wait_all() {
    asm volatile("cp.async.wait_group 0;");
}

// Swizzled float4-index within a 512-float row (head g, chunk c4 0..15):
// (c4+g)&15 skew -> conflict-free g-parallel reads, 1-cyc dec broadcasts.
__device__ __forceinline__ int sw_idx(int g, int c4) {
    return g * 16 + ((c4 + g) & 15);
}

// ---------------------------------------------------------------------------
// Fused kernel = R11 champion structure (47.6us) with ONE change:
// staging via cp.async (LDGSTS) instead of LDG->reg->STS, shortening the
// store-idle prologue. Grid: 1024 blocks = (b:4)x(t:8)x(hwtile:16)x(qh:2),
// 128 threads, 52KB smem -> 4 blk/SM. Streaming __stcs stores (proven R14).
//
// Timeline per block:
//   cp.async stage enc(32KB)+dec(16KB)   [store-idle, shortened]
//   A(q0..3) -> sc0                      [store-idle]
//   INTERLEAVED: 16 steps, each = 1 c4-step of A(q4..7) (regs only)
//                + 4 B-rows of q0..3 (streaming stores)
//   acc -> sc1 ; sync
//   B(q4..7) from sc1                    [stores]
// ---------------------------------------------------------------------------
__global__ void __launch_bounds__(128, 4) heatmap_fused(
    const float* __restrict__ dec,   // (4, 20, 8, 512)
    const float* __restrict__ enc,   // (4, 8, 256, 512)
    const float* __restrict__ Wm,    // (8, 512)
    const float* __restrict__ bias,  // (512,)
    float* __restrict__ out)         // (4, 16, 8, 256, 512)
{
    extern __shared__ char smem_raw[];
    ulonglong2* enc_s = reinterpret_cast<ulonglong2*>(smem_raw);            // 32 KB
    ulonglong2* dec_s = reinterpret_cast<ulonglong2*>(smem_raw + 32768);    // 16 KB
    float*      sc0   = reinterpret_cast<float*>(smem_raw + 49152);         //  2 KB
    float*      sc1   = reinterpret_cast<float*>(smem_raw + 51200);         //  2 KB

    const int tid = threadIdx.x;
    const int bid = blockIdx.x;
    const int qh  = bid & 1;             // q half-of-16: q0 = qh*8
    const int hwt = (bid >> 1) & 15;     // hw tile (16 positions)
    const int t   = (bid >> 5) & 7;
    const int b   = bid >> 8;

    const uint32_t enc_sb = (uint32_t)__cvta_generic_to_shared(enc_s);
    const uint32_t dec_sb = (uint32_t)__cvta_generic_to_shared(dec_s);

    // ---- cp.async stage enc tile: 16 hw rows x 128 float4, swizzled ----
    {
        const float* encg = enc + ((size_t)((b * NT + t) * NHW + hwt * HWT)) * 512;
#pragma unroll
        for (int k = 0; k < 16; k++) {
            int i = tid + k * 128;           // 0..2047
            int hwl = i >> 7;
            int j   = i & 127;
            cp16(enc_sb + (hwl * 128 + sw_idx(j >> 4, j & 15)) * 16,
                 encg + (size_t)i * 4);
        }
    }
    // ---- cp.async stage dec tile: 8 q rows x 128 float4, swizzled ----
    {
#pragma unroll
        for (int k = 0; k < 8; k++) {
            int i = tid + k * 128;           // 0..1023
            int q = i >> 7;                  // local q 0..7
            int j = i & 127;
            cp16(dec_sb + (q * 128 + sw_idx(j >> 4, j & 15)) * 16,
                 dec + ((size_t)((b * NQP + qh * QT + q) * NT + t)) * 512 + j * 4);
        }
    }
    cp_commit();

    // W/bias into registers while cp.async is in flight
    const int f4 = tid;
    const unsigned long long* W2 = reinterpret_cast<const unsigned long long*>(Wm);
    unsigned long long wreg[NG][2];
#pragma unroll
    for (int g = 0; g < NG; g++) {
        wreg[g][0] = W2[g * 256 + f4 * 2];
        wreg[g][1] = W2[g * 256 + f4 * 2 + 1];
    }
    const unsigned long long* B2 = reinterpret_cast<const unsigned long long*>(bias);
    const unsigned long long bb0 = B2[f4 * 2];
    const unsigned long long bb1 = B2[f4 * 2 + 1];

    cp_wait_all();
    __syncthreads();

    // Phase-A thread mapping (persistent across both halves)
    const int ga  = tid & 7;
    const int hwa = tid >> 3;               // 0..15
    const ulonglong2* erow = enc_s + hwa * 128;

    // ---- A(q0..3) -> sc0 ----
    {
        unsigned long long acc[4];
#pragma unroll
        for (int q = 0; q < 4; q++) acc[q] = 0ull;
#pragma unroll 4
        for (int c4 = 0; c4 < 16; c4++) {
            const int cc = sw_idx(ga, c4);
            ulonglong2 e = erow[cc];
#pragma unroll
            for (int q = 0; q < 4; q++) {
                ulonglong2 d = dec_s[q * 128 + cc];
                ffma2(acc[q], e.x, d.x);
                ffma2(acc[q], e.y, d.y);
            }
        }
#pragma unroll
        for (int q = 0; q < 4; q++) {
            float lo, hi;
            unpack2(acc[q], lo, hi);
            sc0[(q * HWT + hwa) * NG + ga] = lo + hi;
        }
    }
    __syncthreads();

    // out float4 base: (((b*16 + qh*8)*8+t)*256 + hwt*16)*128 + f4
    float4* out4 = reinterpret_cast<float4*>(out)
        + ((size_t)((b * NQ + qh * QT) * NT + t) * NHW + hwt * HWT) * 128 + f4;
    // local q stride (float4): 8*256*128 = 262144 ; hwl stride: 128

#define B_ROW(scf, r, qofs)                                                        \
    {                                                                              \
        float4 sA = (scf)[(r) * 2 + 0];                                            \
        float4 sB = (scf)[(r) * 2 + 1];                                            \
        unsigned long long a0 = bb0, a1 = bb1;                                     \
        unsigned long long sp;                                                     \
        sp = pack2(sA.x, sA.x); ffma2(a0, sp, wreg[0][0]); ffma2(a1, sp, wreg[0][1]); \
        sp = pack2(sA.y, sA.y); ffma2(a0, sp, wreg[1][0]); ffma2(a1, sp, wreg[1][1]); \
        sp = pack2(sA.z, sA.z); ffma2(a0, sp, wreg[2][0]); ffma2(a1, sp, wreg[2][1]); \
        sp = pack2(sA.w, sA.w); ffma2(a0, sp, wreg[3][0]); ffma2(a1, sp, wreg[3][1]); \
        sp = pack2(sB.x, sB.x); ffma2(a0, sp, wreg[4][0]); ffma2(a1, sp, wreg[4][1]); \
        sp = pack2(sB.y, sB.y); ffma2(a0, sp, wreg[5][0]); ffma2(a1, sp, wreg[5][1]); \
        sp = pack2(sB.z, sB.z); ffma2(a0, sp, wreg[6][0]); ffma2(a1, sp, wreg[6][1]); \
        sp = pack2(sB.w, sB.w); ffma2(a0, sp, wreg[7][0]); ffma2(a1, sp, wreg[7][1]); \
        float4 res;                                                                \
        asm("mov.b64 {%0, %1}, %2;" : "=f"(res.x), "=f"(res.y) : "l"(a0));         \
        asm("mov.b64 {%0, %1}, %2;" : "=f"(res.z), "=f"(res.w) : "l"(a1));         \
        res.x = fmaxf(res.x, 0.f);                                                 \
        res.y = fmaxf(res.y, 0.f);                                                 \
        res.z = fmaxf(res.z, 0.f);                                                 \
        res.w = fmaxf(res.w, 0.f);                                                 \
        const int q_   = ((r) >> 4) + (qofs);                                      \
        const int hwl_ = (r) & 15;                                                 \
        __stcs(&out4[(size_t)q_ * 262144 + hwl_ * 128], res);                      \
    }

    // ---- INTERLEAVED: A(q4..7) c4-steps woven between B(q0..3) rows ----
    {
        unsigned long long acc2[4];
#pragma unroll
        for (int q = 0; q < 4; q++) acc2[q] = 0ull;

        const float4* scf0 = reinterpret_cast<const float4*>(sc0);

#pragma unroll 2
        for (int s = 0; s < 16; s++) {
            // one c4-step of A(q4..7) — registers only
            const int cc = sw_idx(ga, s);
            ulonglong2 e = erow[cc];
#pragma unroll
            for (int q = 0; q < 4; q++) {
                ulonglong2 d = dec_s[(4 + q) * 128 + cc];
                ffma2(acc2[q], e.x, d.x);
                ffma2(acc2[q], e.y, d.y);
            }
            // four B rows of q0..3 — streaming stores
#pragma unroll
            for (int rr = 0; rr < 4; rr++) {
                B_ROW(scf0, s * 4 + rr, 0);
            }
        }

        // flush A(q4..7) accumulators to the second score buffer
#pragma unroll
        for (int q = 0; q < 4; q++) {
            float lo, hi;
            unpack2(acc2[q], lo, hi);
            sc1[(q * HWT + hwa) * NG + ga] = lo + hi;
        }
    }
    __syncthreads();

    // ---- B(q4..7) from sc1 ----
    {
        const float4* scf1 = reinterpret_cast<const float4*>(sc1);
#pragma unroll 4
        for (int r = 0; r < 64; r++) {
            B_ROW(scf1, r, 4);
        }
    }
#undef B_ROW
}

extern "C" void kernel_launch(void* const* d_in, const int* in_sizes, int n_in,
                              void* d_out, int out_size)
{
    const float* dec  = (const float*)d_in[0];  // (4,20,8,512)
    const float* enc  = (const float*)d_in[1];  // (4,8,16,16,512)
    const float* Wm   = (const float*)d_in[2];  // (8,512)
    const float* bias = (const float*)d_in[3];  // (512,)
    float* out = (float*)d_out;                 // (4,16,8,16,16,512)

    const int smem = 52 * 1024;
    cudaFuncSetAttribute(heatmap_fused,
                         cudaFuncAttributeMaxDynamicSharedMemorySize, smem);

    // 1024 blocks = (b:4)x(t:8)x(hwtile:16)x(qh:2)
    heatmap_fused<<<NB * NT * (NHW / HWT) * 2, 128, smem>>>(dec, enc, Wm, bias, out);
}